// round 16
// baseline (speedup 1.0000x reference)
#include <cuda_runtime.h>
#include <math.h>
#include <stdint.h>

// Problem constants
#define kB   512
#define kN   256
#define kC   128
#define kH   4
#define kHD  32
#define kNW  64

// Scratch (device globals: no runtime allocation allowed)
__device__ __align__(16) float g_q[(size_t)kB * kH * kN * kHD];
__device__ __align__(16) float g_k[(size_t)kB * kH * kN * kHD];
__device__ __align__(16) float g_v[(size_t)kB * kH * kN * kHD];
__device__ __align__(16) float g_ao[(size_t)kB * kN * kC];      // tf32-rounded by attn
__device__ __align__(16) float g_biasS[(size_t)kH * kN * kN];   // 1 MB, bias*log2e
__device__ __align__(16) float g_maskS[(size_t)kNW * kN * kN];  // 16 MB, mask*log2e
__device__ __align__(16) float g_xt[(size_t)kB * kN * kC];      // tf32-rounded x
__device__ __align__(16) float g_wqkv[3 * kC * kC];             // tf32-rounded qkv_w
__device__ __align__(16) float g_wproj[kC * kC];                // tf32-rounded proj_w

#define LOG2E 1.4426950408889634f

// ---------------------------------------------------------------------------
// TF32 / ldmatrix / cp.async helpers
// ---------------------------------------------------------------------------
__device__ __forceinline__ uint32_t f2tf32(float f) {
    uint32_t u;
    asm("cvt.rna.tf32.f32 %0, %1;" : "=r"(u) : "f"(f));
    return u;
}

__device__ __forceinline__ float ex2f(float x) {
    float y;
    asm("ex2.approx.f32 %0, %1;" : "=f"(y) : "f"(x));
    return y;
}

__device__ __forceinline__ void mma_tf32(
    float* c,
    uint32_t a0, uint32_t a1, uint32_t a2, uint32_t a3,
    uint32_t b0, uint32_t b1)
{
    asm volatile(
        "mma.sync.aligned.m16n8k8.row.col.f32.tf32.tf32.f32 "
        "{%0,%1,%2,%3}, {%4,%5,%6,%7}, {%8,%9}, {%0,%1,%2,%3};"
        : "+f"(c[0]), "+f"(c[1]), "+f"(c[2]), "+f"(c[3])
        : "r"(a0), "r"(a1), "r"(a2), "r"(a3), "r"(b0), "r"(b1));
}

__device__ __forceinline__ uint32_t smem_u32(const void* p) {
    return (uint32_t)__cvta_generic_to_shared(p);
}

__device__ __forceinline__ void ldsm_x4(
    uint32_t& r0, uint32_t& r1, uint32_t& r2, uint32_t& r3, uint32_t a)
{
    asm volatile("ldmatrix.sync.aligned.m8n8.x4.shared.b16 {%0,%1,%2,%3}, [%4];"
        : "=r"(r0), "=r"(r1), "=r"(r2), "=r"(r3) : "r"(a));
}

__device__ __forceinline__ void cp16(uint32_t dst, const void* src) {
    asm volatile("cp.async.cg.shared.global [%0], [%1], 16;" :: "r"(dst), "l"(src));
}
#define CP_COMMIT() asm volatile("cp.async.commit_group;")
#define CP_WAIT(N)  asm volatile("cp.async.wait_group %0;" :: "n"(N))

// ---------------------------------------------------------------------------
// cvt: pre-round x, qkv_w, proj_w to tf32 (stored as fp32 bits).
// ---------------------------------------------------------------------------
#define X_F4  4194304
#define QW_F4 12288
#define PW_F4 4096
__global__ __launch_bounds__(256) void cvt_kernel(
    const float* __restrict__ x, const float* __restrict__ qw,
    const float* __restrict__ pw)
{
    int i = blockIdx.x * 256 + threadIdx.x;
    const float4* src;
    float4* dst;
    int off;
    if (i < X_F4) { src = (const float4*)x; dst = (float4*)g_xt; off = i; }
    else if (i < X_F4 + QW_F4) { src = (const float4*)qw; dst = (float4*)g_wqkv; off = i - X_F4; }
    else if (i < X_F4 + QW_F4 + PW_F4) { src = (const float4*)pw; dst = (float4*)g_wproj; off = i - X_F4 - QW_F4; }
    else return;
    float4 v = src[off];
    float4 o;
    o.x = __uint_as_float(f2tf32(v.x));
    o.y = __uint_as_float(f2tf32(v.y));
    o.z = __uint_as_float(f2tf32(v.z));
    o.w = __uint_as_float(f2tf32(v.w));
    dst[off] = o;
}

// ---------------------------------------------------------------------------
// prep: g_maskS = mask*log2e (float4, blocks 0..4095);
//       g_biasS[h][idx] = table[ridx[idx]][h]*log2e (blocks 4096..4351).
// ---------------------------------------------------------------------------
#define MASK_F4 1048576
__global__ __launch_bounds__(256) void prep_kernel(
    const float* __restrict__ mask, const float* __restrict__ table,
    const int* __restrict__ ridx)
{
    int i = blockIdx.x * 256 + threadIdx.x;
    if (i < MASK_F4) {
        float4 mv = ((const float4*)mask)[i];
        float4 o;
        o.x = mv.x * LOG2E; o.y = mv.y * LOG2E;
        o.z = mv.z * LOG2E; o.w = mv.w * LOG2E;
        ((float4*)g_maskS)[i] = o;
    } else {
        int idx = i - MASK_F4;          // 0..65535
        if (idx < 65536) {
            int r = ridx[idx];
#pragma unroll
            for (int h = 0; h < kH; h++)
                g_biasS[h * 65536 + idx] = table[r * kH + h] * LOG2E;
        }
    }
}

// ---------------------------------------------------------------------------
// TF32 MMA GEMM body: C[128m x 128n], A @ B^T.
// Inputs are PRE-ROUNDED tf32 values in fp32 bits -> cp.async staging, MMA
// truncation is exact. 3-stage pipeline, K chunks of 32, ldmatrix frags.
// Stage schedule: k0->s0, k1->s1, k2->s2, k3->s0. Final compute uses s0.
// smem: As[3][128][36] + Bs[3][128][36] = 110592 B.
// ---------------------------------------------------------------------------
#define GPAD 36
#define NSTAGE 3
#define STAGE_W (128 * GPAD)
#define GEMM_SMEM (NSTAGE * 2 * STAGE_W * 4)

struct MmaAcc { float c[4][4][4]; };   // [mi][ni][frag]

__device__ __forceinline__ void gemm_load_stage(
    const float* __restrict__ A, const float* __restrict__ B,
    int m0, int kc, int st, int tid, uint32_t sA, uint32_t sB)
{
#pragma unroll
    for (int i = 0; i < 4; i++) {
        int gx = tid + 256 * i;            // 0..1023
        int r = gx >> 3, c4 = (gx & 7) * 4;
        uint32_t so = (uint32_t)((st * STAGE_W + r * GPAD + c4) * 4);
        cp16(sA + so, A + (size_t)(m0 + r) * kC + kc * 32 + c4);
        cp16(sB + so, B + (size_t)r * kC + kc * 32 + c4);
    }
    CP_COMMIT();
}

__device__ __forceinline__ void gemm_compute_stage(
    int st, uint32_t sA, uint32_t sB, uint32_t a_off, uint32_t b_off, MmaAcc& R)
{
    uint32_t base_a = sA + (uint32_t)(st * STAGE_W * 4) + a_off;
    uint32_t base_b = sB + (uint32_t)(st * STAGE_W * 4) + b_off;
#pragma unroll
    for (int k8 = 0; k8 < 4; k8++) {
        uint32_t colo = (uint32_t)(k8 * 8 * 4);
        uint32_t af[4][4], bf[4][2];
#pragma unroll
        for (int mi = 0; mi < 4; mi++)
            ldsm_x4(af[mi][0], af[mi][1], af[mi][2], af[mi][3],
                    base_a + colo + (uint32_t)(mi * 16 * GPAD * 4));
#pragma unroll
        for (int ni0 = 0; ni0 < 4; ni0 += 2)
            ldsm_x4(bf[ni0][0], bf[ni0][1], bf[ni0 + 1][0], bf[ni0 + 1][1],
                    base_b + colo + (uint32_t)(ni0 * 8 * GPAD * 4));
#pragma unroll
        for (int mi = 0; mi < 4; mi++)
#pragma unroll
            for (int ni = 0; ni < 4; ni++)
                mma_tf32(R.c[mi][ni],
                         af[mi][0], af[mi][1], af[mi][2], af[mi][3],
                         bf[ni][0], bf[ni][1]);
    }
}

__device__ __forceinline__ void mma_gemm_body(
    const float* __restrict__ A, const float* __restrict__ B,
    int m0, MmaAcc& R)
{
    extern __shared__ uint32_t smem_u[];
    uint32_t* As = smem_u;
    uint32_t* Bs = smem_u + NSTAGE * STAGE_W;

    int tid = threadIdx.x;
    int lane = tid & 31;
    int wid = tid >> 5;
    int wm = wid & 1;
    int wn = wid >> 1;

#pragma unroll
    for (int mi = 0; mi < 4; mi++)
#pragma unroll
        for (int ni = 0; ni < 4; ni++)
#pragma unroll
            for (int f = 0; f < 4; f++) R.c[mi][ni][f] = 0.f;

    uint32_t sA = smem_u32(As), sB = smem_u32(Bs);

    int lr8 = lane & 7;
    int g = lane >> 3;
    uint32_t a_off = (uint32_t)(((wm * 64 + lr8 + (g & 1) * 8) * GPAD + (g >> 1) * 4) * 4);
    uint32_t b_off = (uint32_t)(((wn * 32 + (g >> 1) * 8 + lr8) * GPAD + (g & 1) * 4) * 4);

    gemm_load_stage(A, B, m0, 0, 0, tid, sA, sB);
    gemm_load_stage(A, B, m0, 1, 1, tid, sA, sB);

    CP_WAIT(1); __syncthreads();
    gemm_load_stage(A, B, m0, 2, 2, tid, sA, sB);
    gemm_compute_stage(0, sA, sB, a_off, b_off, R);

    CP_WAIT(1); __syncthreads();
    gemm_load_stage(A, B, m0, 3, 0, tid, sA, sB);   // k3 -> stage 0
    gemm_compute_stage(1, sA, sB, a_off, b_off, R);

    CP_WAIT(1); __syncthreads();
    gemm_compute_stage(2, sA, sB, a_off, b_off, R);

    CP_WAIT(0); __syncthreads();
    gemm_compute_stage(0, sA, sB, a_off, b_off, R); // k3 lives in stage 0
}

// ---------------------------------------------------------------------------
// QKV GEMM: grid (1024, 3). A = g_xt, B = g_wqkv. Scatter to [b][h][n][d].
// ---------------------------------------------------------------------------
__global__ __launch_bounds__(256) void qkv_gemm_kernel(const float* __restrict__ bias)
{
    int m0 = blockIdx.x * 128;
    int part = blockIdx.y;
    int j0 = part * 128;

    MmaAcc R;
    mma_gemm_body(g_xt, g_wqkv + (size_t)j0 * kC, m0, R);

    int lane = threadIdx.x & 31;
    int wid = threadIdx.x >> 5;
    int wm = wid & 1, wn = wid >> 1;
    int h = wn;
    float* dst = (part == 0) ? g_q : ((part == 1) ? g_k : g_v);

#pragma unroll
    for (int ni = 0; ni < 4; ni++) {
        int col = wn * 32 + ni * 8 + 2 * (lane & 3);
        int d = col & 31;
        float b0 = bias[j0 + col], b1 = bias[j0 + col + 1];
#pragma unroll
        for (int mi = 0; mi < 4; mi++) {
#pragma unroll
            for (int half = 0; half < 2; half++) {
                int m = m0 + wm * 64 + mi * 16 + (lane >> 2) + half * 8;
                int bidx = m >> 8, n = m & 255;
                float2 o;
                o.x = R.c[mi][ni][half * 2 + 0] + b0;
                o.y = R.c[mi][ni][half * 2 + 1] + b1;
                *(float2*)(dst + ((size_t)((bidx * kH + h) * kN + n)) * kHD + d) = o;
            }
        }
    }
}

// ---------------------------------------------------------------------------
// Proj GEMM: grid (1024). A = g_ao (pre-rounded), B = g_wproj.
// ---------------------------------------------------------------------------
__global__ __launch_bounds__(256) void proj_gemm_kernel(
    const float* __restrict__ bias, float* __restrict__ out)
{
    int m0 = blockIdx.x * 128;

    MmaAcc R;
    mma_gemm_body(g_ao, g_wproj, m0, R);

    int lane = threadIdx.x & 31;
    int wid = threadIdx.x >> 5;
    int wm = wid & 1, wn = wid >> 1;

#pragma unroll
    for (int ni = 0; ni < 4; ni++) {
        int col = wn * 32 + ni * 8 + 2 * (lane & 3);
        float b0 = bias[col], b1 = bias[col + 1];
#pragma unroll
        for (int mi = 0; mi < 4; mi++) {
#pragma unroll
            for (int half = 0; half < 2; half++) {
                int m = m0 + wm * 64 + mi * 16 + (lane >> 2) + half * 8;
                float2 o;
                o.x = R.c[mi][ni][half * 2 + 0] + b0;
                o.y = R.c[mi][ni][half * 2 + 1] + b1;
                *(float2*)(out + (size_t)m * kC + col) = o;
            }
        }
    }
}

// ---------------------------------------------------------------------------
// Tensor-core attention with ldmatrix fragment loads.
// Softmax via ex2 (log2e pre-folded into q-scale, g_biasS, g_maskS).
// Side inputs are two small L2-resident streams (1MB bias + 16MB mask).
// __launch_bounds__(256, 2) caps regs at 128 so 2 blocks/SM fit the register
// file (the R13 regression was 136 regs -> 1 block/SM).
// smem: Kt[256][36] + Vt2[32][260] + Ps[8][32][36] = 107008 B (2/SM fits).
// ---------------------------------------------------------------------------
#define VPAD 260
#define ATTN_SMEM ((256 * 36 + 32 * VPAD + 8 * 32 * 36) * 4)

__global__ __launch_bounds__(256, 2) void attn_mma_kernel()
{
    extern __shared__ uint32_t sm_u[];
    uint32_t* Kt = sm_u;                          // [key][36]
    uint32_t* Vt2 = sm_u + 256 * 36;              // [d][260]
    uint32_t* PsAll = sm_u + 256 * 36 + 32 * VPAD;

    int tid = threadIdx.x;
    int lane = tid & 31;
    int wid = tid >> 5;
    int grp = lane >> 2;       // 0..7
    int j = lane & 3;          // 0..3
    uint32_t* Ps = PsAll + wid * (32 * 36);

    int bh = blockIdx.x;
    int b = bh >> 2, h = bh & 3;

    // Stage K -> Kt[key][36], V -> Vt2[d][260] (transposed), tf32
    const float* kp = g_k + (size_t)bh * (kN * kHD);
    const float* vp = g_v + (size_t)bh * (kN * kHD);
#pragma unroll
    for (int i = 0; i < 8; i++) {
        int f4 = tid + 256 * i;        // 0..2047
        int key = f4 >> 3, c = (f4 & 7) * 4;
        float4 kv = ((const float4*)kp)[f4];
        float4 vv = ((const float4*)vp)[f4];
        uint4 kt;
        kt.x = f2tf32(kv.x); kt.y = f2tf32(kv.y);
        kt.z = f2tf32(kv.z); kt.w = f2tf32(kv.w);
        *(uint4*)(Kt + key * 36 + c) = kt;
        Vt2[(c + 0) * VPAD + key] = f2tf32(vv.x);
        Vt2[(c + 1) * VPAD + key] = f2tf32(vv.y);
        Vt2[(c + 2) * VPAD + key] = f2tf32(vv.z);
        Vt2[(c + 3) * VPAD + key] = f2tf32(vv.w);
    }

    // Q fragments (scale * log2e folded in)
    const float scale = 0.17677669529663688f * LOG2E;
    uint32_t qa[2][4][4];
    const float* qbase = g_q + (size_t)bh * (kN * kHD);
#pragma unroll
    for (int mt = 0; mt < 2; mt++)
#pragma unroll
        for (int ks = 0; ks < 4; ks++) {
            const float* qp = qbase + (wid * 32 + mt * 16 + grp) * kHD + ks * 8 + j;
            qa[mt][ks][0] = f2tf32(qp[0] * scale);
            qa[mt][ks][1] = f2tf32(qp[8 * kHD] * scale);
            qa[mt][ks][2] = f2tf32(qp[4] * scale);
            qa[mt][ks][3] = f2tf32(qp[8 * kHD + 4] * scale);
        }
    __syncthreads();

    // ldmatrix lane addresses
    int lr8 = lane & 7;
    int g = lane >> 3;
    uint32_t k_base = smem_u32(Kt + lr8 * 36 + g * 4);
    uint32_t p_base = smem_u32(Ps + (lr8 + (g & 1) * 8) * 36 + (g >> 1) * 4);
    uint32_t v_base = smem_u32(Vt2 + ((g >> 1) * 8 + lr8) * VPAD + (g & 1) * 4);

    float oacc[2][4][4];
#pragma unroll
    for (int mt = 0; mt < 2; mt++)
#pragma unroll
        for (int dt = 0; dt < 4; dt++)
#pragma unroll
            for (int f = 0; f < 4; f++) oacc[mt][dt][f] = 0.f;
    float rs[2][2] = {{0.f, 0.f}, {0.f, 0.f}};

    const float* biasp = g_biasS + (size_t)h * 65536;
    const float* maskp = g_maskS + (size_t)(b & (kNW - 1)) * 65536;

#pragma unroll 1
    for (int kc = 0; kc < 8; kc++) {
        // S = Q * K_chunk^T
        float sc[2][4][4];
#pragma unroll
        for (int mt = 0; mt < 2; mt++)
#pragma unroll
            for (int nt = 0; nt < 4; nt++)
#pragma unroll
                for (int f = 0; f < 4; f++) sc[mt][nt][f] = 0.f;

#pragma unroll
        for (int nt = 0; nt < 4; nt++) {
            uint32_t bf[4][2];
            uint32_t rowo = (uint32_t)((kc * 32 + nt * 8) * 36 * 4);
            ldsm_x4(bf[0][0], bf[0][1], bf[1][0], bf[1][1], k_base + rowo);
            ldsm_x4(bf[2][0], bf[2][1], bf[3][0], bf[3][1], k_base + rowo + 16 * 4);
#pragma unroll
            for (int ks = 0; ks < 4; ks++) {
                mma_tf32(sc[0][nt], qa[0][ks][0], qa[0][ks][1],
                         qa[0][ks][2], qa[0][ks][3], bf[ks][0], bf[ks][1]);
                mma_tf32(sc[1][nt], qa[1][ks][0], qa[1][ks][1],
                         qa[1][ks][2], qa[1][ks][3], bf[ks][0], bf[ks][1]);
            }
        }

        // bias+mask add + ex2 + store P (tf32, packed uint2) to warp-private Ps
#pragma unroll
        for (int mt = 0; mt < 2; mt++)
#pragma unroll
            for (int nt = 0; nt < 4; nt++) {
                int row = wid * 32 + mt * 16 + grp;
                int col = kc * 32 + nt * 8 + 2 * j;
                float2 bi0 = *(const float2*)(biasp + row * 256 + col);
                float2 bi1 = *(const float2*)(biasp + (row + 8) * 256 + col);
                float2 ms0 = *(const float2*)(maskp + row * 256 + col);
                float2 ms1 = *(const float2*)(maskp + (row + 8) * 256 + col);
                float p0 = ex2f(sc[mt][nt][0] + bi0.x + ms0.x);
                float p1 = ex2f(sc[mt][nt][1] + bi0.y + ms0.y);
                float p2 = ex2f(sc[mt][nt][2] + bi1.x + ms1.x);
                float p3 = ex2f(sc[mt][nt][3] + bi1.y + ms1.y);
                rs[mt][0] += p0 + p1;
                rs[mt][1] += p2 + p3;
                int lr = mt * 16 + grp, lc = nt * 8 + 2 * j;
                uint2 u0, u1;
                u0.x = f2tf32(p0); u0.y = f2tf32(p1);
                u1.x = f2tf32(p2); u1.y = f2tf32(p3);
                *(uint2*)(Ps + lr * 36 + lc) = u0;
                *(uint2*)(Ps + (lr + 8) * 36 + lc) = u1;
            }
        __syncwarp();

        // O += P * V_chunk
#pragma unroll
        for (int ks = 0; ks < 4; ks++) {
            int kb = kc * 32 + ks * 8;
            uint32_t a0[4], a1[4];
            uint32_t pcolo = (uint32_t)(ks * 8 * 4);
            ldsm_x4(a0[0], a0[1], a0[2], a0[3], p_base + pcolo);
            ldsm_x4(a1[0], a1[1], a1[2], a1[3], p_base + pcolo + (uint32_t)(16 * 36 * 4));
            uint32_t bf[4][2];
            uint32_t vcolo = (uint32_t)(kb * 4);
            ldsm_x4(bf[0][0], bf[0][1], bf[1][0], bf[1][1], v_base + vcolo);
            ldsm_x4(bf[2][0], bf[2][1], bf[3][0], bf[3][1],
                    v_base + vcolo + (uint32_t)(16 * VPAD * 4));
#pragma unroll
            for (int dt = 0; dt < 4; dt++) {
                mma_tf32(oacc[0][dt], a0[0], a0[1], a0[2], a0[3], bf[dt][0], bf[dt][1]);
                mma_tf32(oacc[1][dt], a1[0], a1[1], a1[2], a1[3], bf[dt][0], bf[dt][1]);
            }
        }
        __syncwarp();
    }

    // Row-sum reduce across the quad and normalize; write tf32-rounded.
#pragma unroll
    for (int mt = 0; mt < 2; mt++)
#pragma unroll
        for (int hf = 0; hf < 2; hf++) {
            float v = rs[mt][hf];
            v += __shfl_xor_sync(0xFFFFFFFF, v, 1);
            v += __shfl_xor_sync(0xFFFFFFFF, v, 2);
            rs[mt][hf] = 1.f / v;
        }

#pragma unroll
    for (int mt = 0; mt < 2; mt++) {
        int row = wid * 32 + mt * 16 + grp;
#pragma unroll
        for (int dt = 0; dt < 4; dt++) {
            int col = h * 32 + dt * 8 + 2 * j;
            float2 o0, o1;
            o0.x = __uint_as_float(f2tf32(oacc[mt][dt][0] * rs[mt][0]));
            o0.y = __uint_as_float(f2tf32(oacc[mt][dt][1] * rs[mt][0]));
            o1.x = __uint_as_float(f2tf32(oacc[mt][dt][2] * rs[mt][1]));
            o1.y = __uint_as_float(f2tf32(oacc[mt][dt][3] * rs[mt][1]));
            *(float2*)(g_ao + ((size_t)b * 256 + row) * kC + col) = o0;
            *(float2*)(g_ao + ((size_t)b * 256 + row + 8) * kC + col) = o1;
        }
    }
}

// ---------------------------------------------------------------------------
extern "C" void kernel_launch(void* const* d_in, const int* in_sizes, int n_in,
                              void* d_out, int out_size)
{
    const float* x      = (const float*)d_in[0];
    const float* mask   = (const float*)d_in[1];
    const float* qkv_w  = (const float*)d_in[2];
    const float* qkv_b  = (const float*)d_in[3];
    const float* proj_w = (const float*)d_in[4];
    const float* proj_b = (const float*)d_in[5];
    const float* table  = (const float*)d_in[6];
    const int*   ridx   = (const int*)d_in[7];
    float* out = (float*)d_out;

    (void)in_sizes; (void)n_in; (void)out_size;

    cudaFuncSetAttribute((const void*)qkv_gemm_kernel,
                         cudaFuncAttributeMaxDynamicSharedMemorySize, GEMM_SMEM);
    cudaFuncSetAttribute((const void*)proj_gemm_kernel,
                         cudaFuncAttributeMaxDynamicSharedMemorySize, GEMM_SMEM);
    cudaFuncSetAttribute((const void*)attn_mma_kernel,
                         cudaFuncAttributeMaxDynamicSharedMemorySize, ATTN_SMEM);

    cvt_kernel<<<16448, 256>>>(x, qkv_w, proj_w);
    prep_kernel<<<4352, 256>>>(mask, table, ridx);
    qkv_gemm_kernel<<<dim3(1024, 3), 256, GEMM_SMEM>>>(qkv_b);
    attn_mma_kernel<<<2048, 256, ATTN_SMEM>>>();
    proj_gemm_kernel<<<1024, 256, GEMM_SMEM>>>(proj_b, out);
}

// round 17
// speedup vs baseline: 1.1977x; 1.1977x over previous
#include <cuda_runtime.h>
#include <math.h>
#include <stdint.h>

// Problem constants
#define kB   512
#define kN   256
#define kC   128
#define kH   4
#define kHD  32
#define kNW  64

// Scratch (device globals: no runtime allocation allowed)
__device__ __align__(16) float g_q[(size_t)kB * kH * kN * kHD];
__device__ __align__(16) float g_k[(size_t)kB * kH * kN * kHD];
__device__ __align__(16) float g_v[(size_t)kB * kH * kN * kHD];
__device__ __align__(16) float g_ao[(size_t)kB * kN * kC];      // tf32-rounded by attn
__device__ __align__(16) float g_bmp[(size_t)256 * 8 * 8 * 256 * 4]; // 64MB frag-ordered (mask+bias)*log2e
__device__ __align__(16) float g_xt[(size_t)kB * kN * kC];      // tf32-rounded x
__device__ __align__(16) float g_wqkv[3 * kC * kC];             // tf32-rounded qkv_w
__device__ __align__(16) float g_wproj[kC * kC];                // tf32-rounded proj_w

#define LOG2E 1.4426950408889634f

// ---------------------------------------------------------------------------
// TF32 / ldmatrix / cp.async helpers
// ---------------------------------------------------------------------------
__device__ __forceinline__ uint32_t f2tf32(float f) {
    uint32_t u;
    asm("cvt.rna.tf32.f32 %0, %1;" : "=r"(u) : "f"(f));
    return u;
}

__device__ __forceinline__ float ex2f(float x) {
    float y;
    asm("ex2.approx.f32 %0, %1;" : "=f"(y) : "f"(x));
    return y;
}

__device__ __forceinline__ void mma_tf32(
    float* c,
    uint32_t a0, uint32_t a1, uint32_t a2, uint32_t a3,
    uint32_t b0, uint32_t b1)
{
    asm volatile(
        "mma.sync.aligned.m16n8k8.row.col.f32.tf32.tf32.f32 "
        "{%0,%1,%2,%3}, {%4,%5,%6,%7}, {%8,%9}, {%0,%1,%2,%3};"
        : "+f"(c[0]), "+f"(c[1]), "+f"(c[2]), "+f"(c[3])
        : "r"(a0), "r"(a1), "r"(a2), "r"(a3), "r"(b0), "r"(b1));
}

__device__ __forceinline__ uint32_t smem_u32(const void* p) {
    return (uint32_t)__cvta_generic_to_shared(p);
}

__device__ __forceinline__ void ldsm_x4(
    uint32_t& r0, uint32_t& r1, uint32_t& r2, uint32_t& r3, uint32_t a)
{
    asm volatile("ldmatrix.sync.aligned.m8n8.x4.shared.b16 {%0,%1,%2,%3}, [%4];"
        : "=r"(r0), "=r"(r1), "=r"(r2), "=r"(r3) : "r"(a));
}

__device__ __forceinline__ void cp16(uint32_t dst, const void* src) {
    asm volatile("cp.async.cg.shared.global [%0], [%1], 16;" :: "r"(dst), "l"(src));
}
#define CP_COMMIT() asm volatile("cp.async.commit_group;")
#define CP_WAIT(N)  asm volatile("cp.async.wait_group %0;" :: "n"(N))

// ---------------------------------------------------------------------------
// cvt: pre-round x, qkv_w, proj_w to tf32 (stored as fp32 bits).
// ---------------------------------------------------------------------------
#define X_F4  4194304
#define QW_F4 12288
#define PW_F4 4096
__global__ __launch_bounds__(256) void cvt_kernel(
    const float* __restrict__ x, const float* __restrict__ qw,
    const float* __restrict__ pw)
{
    int i = blockIdx.x * 256 + threadIdx.x;
    const float4* src;
    float4* dst;
    int off;
    if (i < X_F4) { src = (const float4*)x; dst = (float4*)g_xt; off = i; }
    else if (i < X_F4 + QW_F4) { src = (const float4*)qw; dst = (float4*)g_wqkv; off = i - X_F4; }
    else if (i < X_F4 + QW_F4 + PW_F4) { src = (const float4*)pw; dst = (float4*)g_wproj; off = i - X_F4 - QW_F4; }
    else return;
    float4 v = src[off];
    float4 o;
    o.x = __uint_as_float(f2tf32(v.x));
    o.y = __uint_as_float(f2tf32(v.y));
    o.z = __uint_as_float(f2tf32(v.z));
    o.w = __uint_as_float(f2tf32(v.w));
    dst[off] = o;
}

// ---------------------------------------------------------------------------
// prep_bmp: fragment-ordered combined table.
// g_bmp float4 index: (((wh*8 + kc)*8 + mt*4+nt)*256 + tid)
//   where tid = wid*32 + grp*4 + j encodes the consuming thread.
// float4 = bm(row,col), bm(row,col+1), bm(row+8,col), bm(row+8,col+1)
//   row = wid*32 + mt*16 + grp, col = kc*32 + nt*8 + 2j
//   bm(r,c) = (mask[w][r][c] + table[ridx[r][c]][h]) * log2e,  w=wh>>2, h=wh&3
// ---------------------------------------------------------------------------
#define BMP_F4 4194304
__global__ __launch_bounds__(256) void prep_bmp_kernel(
    const float* __restrict__ mask, const float* __restrict__ table,
    const int* __restrict__ ridx)
{
    int idx = blockIdx.x * 256 + threadIdx.x;   // 0..4194303
    int tid4 = idx & 255;
    int mtnt = (idx >> 8) & 7;
    int kc = (idx >> 11) & 7;
    int wh = idx >> 14;                         // 0..255
    int w = wh >> 2, h = wh & 3;
    int wid = tid4 >> 5;
    int lane = tid4 & 31;
    int grp = lane >> 2, j = lane & 3;
    int mt = mtnt >> 2, nt = mtnt & 3;
    int row = wid * 32 + mt * 16 + grp;
    int col = kc * 32 + nt * 8 + 2 * j;

    const float* mrow = mask + (size_t)w * 65536;
    int i00 = row * 256 + col;
    int i10 = (row + 8) * 256 + col;
    float4 o;
    o.x = (mrow[i00]     + table[ridx[i00] * kH + h])     * LOG2E;
    o.y = (mrow[i00 + 1] + table[ridx[i00 + 1] * kH + h]) * LOG2E;
    o.z = (mrow[i10]     + table[ridx[i10] * kH + h])     * LOG2E;
    o.w = (mrow[i10 + 1] + table[ridx[i10 + 1] * kH + h]) * LOG2E;
    ((float4*)g_bmp)[idx] = o;
}

// ---------------------------------------------------------------------------
// TF32 MMA GEMM body: C[128m x 128n], A @ B^T.
// Inputs are PRE-ROUNDED tf32 values in fp32 bits -> cp.async staging, MMA
// truncation is exact. 3-stage pipeline, K chunks of 32, ldmatrix frags.
// Stage schedule: k0->s0, k1->s1, k2->s2, k3->s0. Final compute uses s0.
// smem: As[3][128][36] + Bs[3][128][36] = 110592 B.
// ---------------------------------------------------------------------------
#define GPAD 36
#define NSTAGE 3
#define STAGE_W (128 * GPAD)
#define GEMM_SMEM (NSTAGE * 2 * STAGE_W * 4)

struct MmaAcc { float c[4][4][4]; };   // [mi][ni][frag]

__device__ __forceinline__ void gemm_load_stage(
    const float* __restrict__ A, const float* __restrict__ B,
    int m0, int kc, int st, int tid, uint32_t sA, uint32_t sB)
{
#pragma unroll
    for (int i = 0; i < 4; i++) {
        int gx = tid + 256 * i;            // 0..1023
        int r = gx >> 3, c4 = (gx & 7) * 4;
        uint32_t so = (uint32_t)((st * STAGE_W + r * GPAD + c4) * 4);
        cp16(sA + so, A + (size_t)(m0 + r) * kC + kc * 32 + c4);
        cp16(sB + so, B + (size_t)r * kC + kc * 32 + c4);
    }
    CP_COMMIT();
}

__device__ __forceinline__ void gemm_compute_stage(
    int st, uint32_t sA, uint32_t sB, uint32_t a_off, uint32_t b_off, MmaAcc& R)
{
    uint32_t base_a = sA + (uint32_t)(st * STAGE_W * 4) + a_off;
    uint32_t base_b = sB + (uint32_t)(st * STAGE_W * 4) + b_off;
#pragma unroll
    for (int k8 = 0; k8 < 4; k8++) {
        uint32_t colo = (uint32_t)(k8 * 8 * 4);
        uint32_t af[4][4], bf[4][2];
#pragma unroll
        for (int mi = 0; mi < 4; mi++)
            ldsm_x4(af[mi][0], af[mi][1], af[mi][2], af[mi][3],
                    base_a + colo + (uint32_t)(mi * 16 * GPAD * 4));
#pragma unroll
        for (int ni0 = 0; ni0 < 4; ni0 += 2)
            ldsm_x4(bf[ni0][0], bf[ni0][1], bf[ni0 + 1][0], bf[ni0 + 1][1],
                    base_b + colo + (uint32_t)(ni0 * 8 * GPAD * 4));
#pragma unroll
        for (int mi = 0; mi < 4; mi++)
#pragma unroll
            for (int ni = 0; ni < 4; ni++)
                mma_tf32(R.c[mi][ni],
                         af[mi][0], af[mi][1], af[mi][2], af[mi][3],
                         bf[ni][0], bf[ni][1]);
    }
}

__device__ __forceinline__ void mma_gemm_body(
    const float* __restrict__ A, const float* __restrict__ B,
    int m0, MmaAcc& R)
{
    extern __shared__ uint32_t smem_u[];
    uint32_t* As = smem_u;
    uint32_t* Bs = smem_u + NSTAGE * STAGE_W;

    int tid = threadIdx.x;
    int lane = tid & 31;
    int wid = tid >> 5;
    int wm = wid & 1;
    int wn = wid >> 1;

#pragma unroll
    for (int mi = 0; mi < 4; mi++)
#pragma unroll
        for (int ni = 0; ni < 4; ni++)
#pragma unroll
            for (int f = 0; f < 4; f++) R.c[mi][ni][f] = 0.f;

    uint32_t sA = smem_u32(As), sB = smem_u32(Bs);

    int lr8 = lane & 7;
    int g = lane >> 3;
    uint32_t a_off = (uint32_t)(((wm * 64 + lr8 + (g & 1) * 8) * GPAD + (g >> 1) * 4) * 4);
    uint32_t b_off = (uint32_t)(((wn * 32 + (g >> 1) * 8 + lr8) * GPAD + (g & 1) * 4) * 4);

    gemm_load_stage(A, B, m0, 0, 0, tid, sA, sB);
    gemm_load_stage(A, B, m0, 1, 1, tid, sA, sB);

    CP_WAIT(1); __syncthreads();
    gemm_load_stage(A, B, m0, 2, 2, tid, sA, sB);
    gemm_compute_stage(0, sA, sB, a_off, b_off, R);

    CP_WAIT(1); __syncthreads();
    gemm_load_stage(A, B, m0, 3, 0, tid, sA, sB);   // k3 -> stage 0
    gemm_compute_stage(1, sA, sB, a_off, b_off, R);

    CP_WAIT(1); __syncthreads();
    gemm_compute_stage(2, sA, sB, a_off, b_off, R);

    CP_WAIT(0); __syncthreads();
    gemm_compute_stage(0, sA, sB, a_off, b_off, R); // k3 lives in stage 0
}

// ---------------------------------------------------------------------------
// QKV GEMM: grid (1024, 3). A = g_xt, B = g_wqkv. Scatter to [b][h][n][d].
// ---------------------------------------------------------------------------
__global__ __launch_bounds__(256) void qkv_gemm_kernel(const float* __restrict__ bias)
{
    int m0 = blockIdx.x * 128;
    int part = blockIdx.y;
    int j0 = part * 128;

    MmaAcc R;
    mma_gemm_body(g_xt, g_wqkv + (size_t)j0 * kC, m0, R);

    int lane = threadIdx.x & 31;
    int wid = threadIdx.x >> 5;
    int wm = wid & 1, wn = wid >> 1;
    int h = wn;
    float* dst = (part == 0) ? g_q : ((part == 1) ? g_k : g_v);

#pragma unroll
    for (int ni = 0; ni < 4; ni++) {
        int col = wn * 32 + ni * 8 + 2 * (lane & 3);
        int d = col & 31;
        float b0 = bias[j0 + col], b1 = bias[j0 + col + 1];
#pragma unroll
        for (int mi = 0; mi < 4; mi++) {
#pragma unroll
            for (int half = 0; half < 2; half++) {
                int m = m0 + wm * 64 + mi * 16 + (lane >> 2) + half * 8;
                int bidx = m >> 8, n = m & 255;
                float2 o;
                o.x = R.c[mi][ni][half * 2 + 0] + b0;
                o.y = R.c[mi][ni][half * 2 + 1] + b1;
                *(float2*)(dst + ((size_t)((bidx * kH + h) * kN + n)) * kHD + d) = o;
            }
        }
    }
}

// ---------------------------------------------------------------------------
// Proj GEMM: grid (1024). A = g_ao (pre-rounded), B = g_wproj.
// ---------------------------------------------------------------------------
__global__ __launch_bounds__(256) void proj_gemm_kernel(
    const float* __restrict__ bias, float* __restrict__ out)
{
    int m0 = blockIdx.x * 128;

    MmaAcc R;
    mma_gemm_body(g_ao, g_wproj, m0, R);

    int lane = threadIdx.x & 31;
    int wid = threadIdx.x >> 5;
    int wm = wid & 1, wn = wid >> 1;

#pragma unroll
    for (int ni = 0; ni < 4; ni++) {
        int col = wn * 32 + ni * 8 + 2 * (lane & 3);
        float b0 = bias[col], b1 = bias[col + 1];
#pragma unroll
        for (int mi = 0; mi < 4; mi++) {
#pragma unroll
            for (int half = 0; half < 2; half++) {
                int m = m0 + wm * 64 + mi * 16 + (lane >> 2) + half * 8;
                float2 o;
                o.x = R.c[mi][ni][half * 2 + 0] + b0;
                o.y = R.c[mi][ni][half * 2 + 1] + b1;
                *(float2*)(out + (size_t)m * kC + col) = o;
            }
        }
    }
}

// ---------------------------------------------------------------------------
// Tensor-core attention, L1-load-minimized:
// - bm is FRAGMENT-ORDERED (g_bmp): 1 float4 per (mt,nt) per kc per thread
//   (8 LDG.128/thread/kc vs 32 LDG.64 in the split-table version).
// - blockIdx remapped so the 8 batches sharing a (w,h) bm region are
//   consecutive -> concurrent wave's bmp working set ~9.5MB, L2-resident.
// smem: Kt[256][36] + Vt2[32][260] + Ps[8][32][36] = 107008 B (2/SM fits).
// ---------------------------------------------------------------------------
#define VPAD 260
#define ATTN_SMEM ((256 * 36 + 32 * VPAD + 8 * 32 * 36) * 4)

__global__ __launch_bounds__(256, 2) void attn_mma_kernel()
{
    extern __shared__ uint32_t sm_u[];
    uint32_t* Kt = sm_u;                          // [key][36]
    uint32_t* Vt2 = sm_u + 256 * 36;              // [d][260]
    uint32_t* PsAll = sm_u + 256 * 36 + 32 * VPAD;

    int tid = threadIdx.x;
    int lane = tid & 31;
    int wid = tid >> 5;
    int grp = lane >> 2;       // 0..7
    int j = lane & 3;          // 0..3
    uint32_t* Ps = PsAll + wid * (32 * 36);

    // Block remap: consecutive blocks share (w,h) -> same bmp region
    int bx = blockIdx.x;
    int wh = bx >> 3;          // 0..255
    int rep = bx & 7;          // 0..7
    int w = wh >> 2, h = wh & 3;
    int b = rep * 64 + w;
    int bh = b * 4 + h;

    // Stage K -> Kt[key][36], V -> Vt2[d][260] (transposed), tf32
    const float* kp = g_k + (size_t)bh * (kN * kHD);
    const float* vp = g_v + (size_t)bh * (kN * kHD);
#pragma unroll
    for (int i = 0; i < 8; i++) {
        int f4 = tid + 256 * i;        // 0..2047
        int key = f4 >> 3, c = (f4 & 7) * 4;
        float4 kv = ((const float4*)kp)[f4];
        float4 vv = ((const float4*)vp)[f4];
        uint4 kt;
        kt.x = f2tf32(kv.x); kt.y = f2tf32(kv.y);
        kt.z = f2tf32(kv.z); kt.w = f2tf32(kv.w);
        *(uint4*)(Kt + key * 36 + c) = kt;
        Vt2[(c + 0) * VPAD + key] = f2tf32(vv.x);
        Vt2[(c + 1) * VPAD + key] = f2tf32(vv.y);
        Vt2[(c + 2) * VPAD + key] = f2tf32(vv.z);
        Vt2[(c + 3) * VPAD + key] = f2tf32(vv.w);
    }

    // Q fragments (scale * log2e folded in)
    const float scale = 0.17677669529663688f * LOG2E;
    uint32_t qa[2][4][4];
    const float* qbase = g_q + (size_t)bh * (kN * kHD);
#pragma unroll
    for (int mt = 0; mt < 2; mt++)
#pragma unroll
        for (int ks = 0; ks < 4; ks++) {
            const float* qp = qbase + (wid * 32 + mt * 16 + grp) * kHD + ks * 8 + j;
            qa[mt][ks][0] = f2tf32(qp[0] * scale);
            qa[mt][ks][1] = f2tf32(qp[8 * kHD] * scale);
            qa[mt][ks][2] = f2tf32(qp[4] * scale);
            qa[mt][ks][3] = f2tf32(qp[8 * kHD + 4] * scale);
        }
    __syncthreads();

    // ldmatrix lane addresses
    int lr8 = lane & 7;
    int g = lane >> 3;
    uint32_t k_base = smem_u32(Kt + lr8 * 36 + g * 4);
    uint32_t p_base = smem_u32(Ps + (lr8 + (g & 1) * 8) * 36 + (g >> 1) * 4);
    uint32_t v_base = smem_u32(Vt2 + ((g >> 1) * 8 + lr8) * VPAD + (g & 1) * 4);

    float oacc[2][4][4];
#pragma unroll
    for (int mt = 0; mt < 2; mt++)
#pragma unroll
        for (int dt = 0; dt < 4; dt++)
#pragma unroll
            for (int f = 0; f < 4; f++) oacc[mt][dt][f] = 0.f;
    float rs[2][2] = {{0.f, 0.f}, {0.f, 0.f}};

    // Fragment-ordered bm base for this (w,h) and thread
    const float4* bmp = (const float4*)g_bmp + ((size_t)wh * 8 * 8 * 256) + tid;

#pragma unroll 1
    for (int kc = 0; kc < 8; kc++) {
        // S = Q * K_chunk^T
        float sc[2][4][4];
#pragma unroll
        for (int mt = 0; mt < 2; mt++)
#pragma unroll
            for (int nt = 0; nt < 4; nt++)
#pragma unroll
                for (int f = 0; f < 4; f++) sc[mt][nt][f] = 0.f;

#pragma unroll
        for (int nt = 0; nt < 4; nt++) {
            uint32_t bf[4][2];
            uint32_t rowo = (uint32_t)((kc * 32 + nt * 8) * 36 * 4);
            ldsm_x4(bf[0][0], bf[0][1], bf[1][0], bf[1][1], k_base + rowo);
            ldsm_x4(bf[2][0], bf[2][1], bf[3][0], bf[3][1], k_base + rowo + 16 * 4);
#pragma unroll
            for (int ks = 0; ks < 4; ks++) {
                mma_tf32(sc[0][nt], qa[0][ks][0], qa[0][ks][1],
                         qa[0][ks][2], qa[0][ks][3], bf[ks][0], bf[ks][1]);
                mma_tf32(sc[1][nt], qa[1][ks][0], qa[1][ks][1],
                         qa[1][ks][2], qa[1][ks][3], bf[ks][0], bf[ks][1]);
            }
        }

        // bm add + ex2 + store P (tf32, packed uint2) to warp-private Ps
        const float4* bmk = bmp + (size_t)kc * (8 * 256);
#pragma unroll
        for (int mt = 0; mt < 2; mt++)
#pragma unroll
            for (int nt = 0; nt < 4; nt++) {
                float4 f = bmk[(mt * 4 + nt) * 256];
                float p0 = ex2f(sc[mt][nt][0] + f.x);
                float p1 = ex2f(sc[mt][nt][1] + f.y);
                float p2 = ex2f(sc[mt][nt][2] + f.z);
                float p3 = ex2f(sc[mt][nt][3] + f.w);
                rs[mt][0] += p0 + p1;
                rs[mt][1] += p2 + p3;
                int lr = mt * 16 + grp, lc = nt * 8 + 2 * j;
                uint2 u0, u1;
                u0.x = f2tf32(p0); u0.y = f2tf32(p1);
                u1.x = f2tf32(p2); u1.y = f2tf32(p3);
                *(uint2*)(Ps + lr * 36 + lc) = u0;
                *(uint2*)(Ps + (lr + 8) * 36 + lc) = u1;
            }
        __syncwarp();

        // O += P * V_chunk
#pragma unroll
        for (int ks = 0; ks < 4; ks++) {
            int kb = kc * 32 + ks * 8;
            uint32_t a0[4], a1[4];
            uint32_t pcolo = (uint32_t)(ks * 8 * 4);
            ldsm_x4(a0[0], a0[1], a0[2], a0[3], p_base + pcolo);
            ldsm_x4(a1[0], a1[1], a1[2], a1[3], p_base + pcolo + (uint32_t)(16 * 36 * 4));
            uint32_t bf[4][2];
            uint32_t vcolo = (uint32_t)(kb * 4);
            ldsm_x4(bf[0][0], bf[0][1], bf[1][0], bf[1][1], v_base + vcolo);
            ldsm_x4(bf[2][0], bf[2][1], bf[3][0], bf[3][1],
                    v_base + vcolo + (uint32_t)(16 * VPAD * 4));
#pragma unroll
            for (int dt = 0; dt < 4; dt++) {
                mma_tf32(oacc[0][dt], a0[0], a0[1], a0[2], a0[3], bf[dt][0], bf[dt][1]);
                mma_tf32(oacc[1][dt], a1[0], a1[1], a1[2], a1[3], bf[dt][0], bf[dt][1]);
            }
        }
        __syncwarp();
    }

    // Row-sum reduce across the quad and normalize; write tf32-rounded.
#pragma unroll
    for (int mt = 0; mt < 2; mt++)
#pragma unroll
        for (int hf = 0; hf < 2; hf++) {
            float v = rs[mt][hf];
            v += __shfl_xor_sync(0xFFFFFFFF, v, 1);
            v += __shfl_xor_sync(0xFFFFFFFF, v, 2);
            rs[mt][hf] = 1.f / v;
        }

#pragma unroll
    for (int mt = 0; mt < 2; mt++) {
        int row = wid * 32 + mt * 16 + grp;
#pragma unroll
        for (int dt = 0; dt < 4; dt++) {
            int col = h * 32 + dt * 8 + 2 * j;
            float2 o0, o1;
            o0.x = __uint_as_float(f2tf32(oacc[mt][dt][0] * rs[mt][0]));
            o0.y = __uint_as_float(f2tf32(oacc[mt][dt][1] * rs[mt][0]));
            o1.x = __uint_as_float(f2tf32(oacc[mt][dt][2] * rs[mt][1]));
            o1.y = __uint_as_float(f2tf32(oacc[mt][dt][3] * rs[mt][1]));
            *(float2*)(g_ao + ((size_t)b * 256 + row) * kC + col) = o0;
            *(float2*)(g_ao + ((size_t)b * 256 + row + 8) * kC + col) = o1;
        }
    }
}

// ---------------------------------------------------------------------------
extern "C" void kernel_launch(void* const* d_in, const int* in_sizes, int n_in,
                              void* d_out, int out_size)
{
    const float* x      = (const float*)d_in[0];
    const float* mask   = (const float*)d_in[1];
    const float* qkv_w  = (const float*)d_in[2];
    const float* qkv_b  = (const float*)d_in[3];
    const float* proj_w = (const float*)d_in[4];
    const float* proj_b = (const float*)d_in[5];
    const float* table  = (const float*)d_in[6];
    const int*   ridx   = (const int*)d_in[7];
    float* out = (float*)d_out;

    (void)in_sizes; (void)n_in; (void)out_size;

    cudaFuncSetAttribute((const void*)qkv_gemm_kernel,
                         cudaFuncAttributeMaxDynamicSharedMemorySize, GEMM_SMEM);
    cudaFuncSetAttribute((const void*)proj_gemm_kernel,
                         cudaFuncAttributeMaxDynamicSharedMemorySize, GEMM_SMEM);
    cudaFuncSetAttribute((const void*)attn_mma_kernel,
                         cudaFuncAttributeMaxDynamicSharedMemorySize, ATTN_SMEM);

    cvt_kernel<<<16448, 256>>>(x, qkv_w, proj_w);
    prep_bmp_kernel<<<16384, 256>>>(mask, table, ridx);
    qkv_gemm_kernel<<<dim3(1024, 3), 256, GEMM_SMEM>>>(qkv_b);
    attn_mma_kernel<<<2048, 256, ATTN_SMEM>>>();
    proj_gemm_kernel<<<1024, 256, GEMM_SMEM>>>(proj_b, out);
}